// round 14
// baseline (speedup 1.0000x reference)
#include <cuda_runtime.h>
#include <cuda_fp16.h>
#include <cstdint>

// ============================================================================
// x[32,256,56,56] -> shift2d -> 1x1 conv W[256,256] -> BN -> ReLU
// GEMM: M = 100352, N = 256, K = 256. mma.sync m16n8k16 fp16/fp32.
// R12: two-pass. prep_x writes g_xt = fp16(shift2d(x)) NHWC (W-convert merged).
// Main: N-split CTA = 64 px x 128 cout, 8 warps (2Mx4N, tile 32x32),
// 3 CTAs/SM (85-reg cap), all-cp.async staging, K chunked 64x4.
// ============================================================================
#define CIN    256
#define COUT   256
#define HH     56
#define WWD    56
#define HWSZ   3136
#define NPIX   100352
#define CTA_M  64
#define NHALF  128
#define NTIL   (NPIX / CTA_M)     // 1568
#define GRID   (NTIL * 2)         // 3136
#define KCH    64
#define NCHUNK 4

// main SMEM: A[buf][64 rows][128B] at 0 (2x8KB); B[buf][128 rows][128B]
// at 16384 (2x16KB). XOR-unit swizzled.
#define OFF_B      16384
#define A_BUF_BY   8192
#define B_BUF_BY   16384
#define SMEM_BYTES 49152

// device-global scratch (sanctioned)
__device__ __align__(16) __half g_xt[NPIX * CIN];   // shifted x, NHWC fp16
__device__ __half g_w[COUT * CIN];                  // W * inv, fp16
__device__ float  g_bias[COUT];

#define DEVINL __device__ __forceinline__

DEVINL uint32_t smem_u32(const void* p) {
    uint32_t a;
    asm("{ .reg .u64 t; cvta.to.shared.u64 t, %1; cvt.u32.u64 %0, t; }"
        : "=r"(a) : "l"(p));
    return a;
}

#define CP_ASYNC16(dst_u32, src_ptr) \
    asm volatile("cp.async.cg.shared.global [%0], [%1], 16;" \
        :: "r"(dst_u32), "l"(src_ptr) : "memory")
#define CP_COMMIT() asm volatile("cp.async.commit_group;" ::: "memory")
#define CP_WAIT0()  asm volatile("cp.async.wait_group 0;"  ::: "memory")

#define MMA16816(d, a0, a1, a2, a3, b0, b1) \
    asm volatile("mma.sync.aligned.m16n8k16.row.col.f32.f16.f16.f32 " \
        "{%0,%1,%2,%3}, {%4,%5,%6,%7}, {%8,%9}, {%0,%1,%2,%3};" \
        : "+f"((d)[0]), "+f"((d)[1]), "+f"((d)[2]), "+f"((d)[3]) \
        : "r"(a0), "r"(a1), "r"(a2), "r"(a3), "r"(b0), "r"(b1))

#define LDSM4(r, addr) \
    asm volatile("ldmatrix.sync.aligned.m8n8.x4.shared.b16 {%0,%1,%2,%3}, [%4];" \
        : "=r"((r)[0]), "=r"((r)[1]), "=r"((r)[2]), "=r"((r)[3]) : "r"(addr))

// channel -> shift direction (group starts 0,51,102,153,204)
DEVINL int ch_dir(int c) {
    return (c >= 204) ? 4 : (c >= 153) ? 3 : (c >= 102) ? 2 : (c >= 51) ? 1 : 0;
}

// ============================================================================
// prep_x: g_xt[p][c] = fp16(shift2d(x)); NCHW -> NHWC via SMEM tile.
// Blocks (1568, 4) x 256 thr. W-convert + bias merged onto by==0 blocks.
// ============================================================================
#define XPITCH 66
__global__ void __launch_bounds__(256)
prep_x_kernel(const float* __restrict__ x,
              const float* __restrict__ pw,
              const float* __restrict__ gamma,
              const float* __restrict__ beta,
              const float* __restrict__ rmean,
              const float* __restrict__ rvar)
{
    __shared__ __half s[64 * XPITCH];

    const int pt  = blockIdx.x;
    const int cg  = blockIdx.y;
    const int tid = threadIdx.x;

    // ---- merged W prep: by==0, bx<256 handles W row o=bx ------------------
    if (cg == 0 && pt < COUT && tid < 64) {
        const int o = pt;
        const float inv_o = gamma[o] * rsqrtf(rvar[o] + 1e-5f);
        float4 v = *reinterpret_cast<const float4*>(pw + (size_t)o * CIN + tid * 4);
        __half2 h01 = __floats2half2_rn(v.x * inv_o, v.y * inv_o);
        __half2 h23 = __floats2half2_rn(v.z * inv_o, v.w * inv_o);
        *reinterpret_cast<__half2*>(g_w + (size_t)o * CIN + tid * 4)     = h01;
        *reinterpret_cast<__half2*>(g_w + (size_t)o * CIN + tid * 4 + 2) = h23;
        if (o == 0) {
            #pragma unroll
            for (int j = 0; j < 4; ++j) {
                int c = tid * 4 + j;
                float inv_c = gamma[c] * rsqrtf(rvar[c] + 1e-5f);
                g_bias[c] = beta[c] - rmean[c] * inv_c;
            }
        }
    }

    // ---- load+shift+convert: thread = (pixel, 16-ch slice) ------------------
    const int px = tid & 63;
    const int P  = pt * 64 + px;
    const int bb = P / HWSZ;
    const int rr = P - bb * HWSZ;
    const int hh = rr / WWD;
    const int ww = rr - hh * WWD;
    const float* xb = x + (size_t)bb * CIN * HWSZ;

    int  offs[5];
    bool vald[5];
    {
        const int dxs[5] = {0, 1, -1, 0, 0};
        const int dys[5] = {0, 0, 0, 1, -1};
        #pragma unroll
        for (int d5 = 0; d5 < 5; ++d5) {
            int hs = hh - dys[d5], ws = ww - dxs[d5];
            vald[d5] = ((unsigned)hs < HH) && ((unsigned)ws < WWD);
            offs[d5] = hs * WWD + ws;
        }
    }

    const int cl0 = (tid >> 6) * 16;       // 16 channels per thread
    #pragma unroll
    for (int j = 0; j < 16; ++j) {
        const int cl = cl0 + j;
        const int c  = cg * 64 + cl;
        const int d5 = ch_dir(c);
        float v = vald[d5] ? __ldg(xb + (size_t)c * HWSZ + offs[d5]) : 0.0f;
        s[px * XPITCH + cl] = __float2half_rn(v);
    }
    __syncthreads();

    // ---- write NHWC: 2 x 16B units per thread -------------------------------
    #pragma unroll
    for (int t = 0; t < 2; ++t) {
        const int v   = tid * 2 + t;
        const int pxo = v >> 3;
        const int u   = v & 7;
        const uint32_t* sp = reinterpret_cast<const uint32_t*>(
            s + pxo * XPITCH + u * 8);
        uint4 val = make_uint4(sp[0], sp[1], sp[2], sp[3]);
        *reinterpret_cast<uint4*>(
            g_xt + (size_t)(pt * 64 + pxo) * CIN + cg * 64 + u * 8) = val;
    }
}

// ============================================================================
// main: 256 threads, 8 warps = 2(M) x 4(N), warp tile 32 x 32, all-cp.async.
// 3 CTAs/SM.
// ============================================================================
__global__ void __launch_bounds__(256, 3)
shiftconv_kernel(float* __restrict__ out)
{
    extern __shared__ char smem[];

    const int tid  = threadIdx.x;
    const int warp = tid >> 5;
    const int lane = tid & 31;
    const int gr   = lane >> 2;
    const int lq   = lane & 3;

    const int tile = blockIdx.x >> 1;
    const int nh   = blockIdx.x & 1;        // cout half

    const int warp_m  = (warp & 1) * 32;    // M offset in tile
    const int warp_nl = (warp >> 1) * 32;   // N offset in half

    const uint32_t sA_u32 = smem_u32(smem);
    const uint32_t sB_u32 = smem_u32(smem + OFF_B);

    // ---- ldmatrix per-lane bases --------------------------------------------
    uint32_t a_base[2];
    const uint32_t a_c  = (uint32_t)(lane >> 4);
    const uint32_t a_x7 = (uint32_t)(lane & 7);
    {
        const int ar = lane & 15;
        #pragma unroll
        for (int mi = 0; mi < 2; ++mi)
            a_base[mi] = sA_u32 + (uint32_t)(warp_m + mi * 16 + ar) * 128;
    }
    uint32_t b_base[2];
    const int grp  = lane >> 3;
    const int nrow = lane - ((grp == 1 || grp == 2) ? 8 : (grp == 3) ? 16 : 0);
    const uint32_t b_c  = (uint32_t)(grp & 1);
    const uint32_t b_x7 = (uint32_t)(nrow & 7);
    #pragma unroll
    for (int f16 = 0; f16 < 2; ++f16)
        b_base[f16] = sB_u32 + (uint32_t)(warp_nl + f16 * 16 + nrow) * 128;

    // ---- cp.async staging maps ----------------------------------------------
    // A: 64 rows x 8 units = 512 / 256 thr = 2 per thread
    const int apx = tid >> 2;               // pixel row
    const int au0 = (tid & 3) * 2;          // units au0, au0+1
    const uint32_t a_dst0 = sA_u32 + (uint32_t)apx * 128 +
                            ((((uint32_t)au0)     ^ (uint32_t)(apx & 7)) << 4);
    const uint32_t a_dst1 = sA_u32 + (uint32_t)apx * 128 +
                            ((((uint32_t)au0 + 1) ^ (uint32_t)(apx & 7)) << 4);
    const __half* a_src = g_xt + (size_t)(tile * CTA_M + apx) * CIN + au0 * 8;

    // B: 128 rows x 8 units = 1024 / 256 thr = 4 per thread
    const int bu = tid & 7;
    const int bn = tid >> 3;                // 0..31
    const uint32_t b_st = sB_u32 + (uint32_t)bn * 128 +
                          (((uint32_t)bu ^ (uint32_t)(bn & 7)) << 4);

    auto cp_A = [&](int chunk, int buf) {
        const uint32_t o = (uint32_t)buf * A_BUF_BY;
        const __half* src = a_src + chunk * KCH;
        CP_ASYNC16(a_dst0 + o, src);
        CP_ASYNC16(a_dst1 + o, src + 8);
    };

    auto cp_B = [&](int chunk, int buf) {
        const int c0 = chunk * KCH;
        #pragma unroll
        for (int itn = 0; itn < 4; ++itn) {
            const int n = bn + 32 * itn;
            const uint32_t dst = b_st + (uint32_t)(buf * 128 + 32 * itn) * 128;
            const __half* src = g_w + (size_t)(nh * NHALF + n) * CIN + c0 + bu * 8;
            CP_ASYNC16(dst, src);
        }
    };

    float d[2][4][4];
    #pragma unroll
    for (int mi = 0; mi < 2; ++mi)
        #pragma unroll
        for (int f = 0; f < 4; ++f)
            #pragma unroll
            for (int e = 0; e < 4; ++e) d[mi][f][e] = 0.0f;

    // ---- prologue -----------------------------------------------------------
    cp_A(0, 0);
    cp_B(0, 0);
    CP_COMMIT();

    // ---- main loop: all-async staging ---------------------------------------
    #pragma unroll 1
    for (int i = 0; i < NCHUNK; ++i) {
        const int buf = i & 1;
        CP_WAIT0();
        __syncthreads();                    // A(i), B(i) visible

        if (i < NCHUNK - 1) {
            cp_A(i + 1, buf ^ 1);
            cp_B(i + 1, buf ^ 1);
            CP_COMMIT();                    // full compute block of slack
        }

        {
            const uint32_t aoff = (uint32_t)buf * A_BUF_BY;
            const uint32_t boff = (uint32_t)buf * B_BUF_BY;
            #pragma unroll
            for (int kk = 0; kk < 4; ++kk) {
                uint32_t a[2][4], b[2][4];
                #pragma unroll
                for (int mi = 0; mi < 2; ++mi)
                    LDSM4(a[mi], a_base[mi] + aoff +
                          ((((uint32_t)(2 * kk) + a_c) ^ a_x7) << 4));
                #pragma unroll
                for (int f16 = 0; f16 < 2; ++f16)
                    LDSM4(b[f16], b_base[f16] + boff +
                          ((((uint32_t)(2 * kk) + b_c) ^ b_x7) << 4));
                #pragma unroll
                for (int f16 = 0; f16 < 2; ++f16)
                    #pragma unroll
                    for (int mi = 0; mi < 2; ++mi) {
                        MMA16816(d[mi][2*f16],     a[mi][0], a[mi][1], a[mi][2], a[mi][3],
                                 b[f16][0], b[f16][1]);
                        MMA16816(d[mi][2*f16 + 1], a[mi][0], a[mi][1], a[mi][2], a[mi][3],
                                 b[f16][2], b[f16][3]);
                    }
            }
        }
    }

    // ---- epilogue: bias + relu + store --------------------------------------
    #pragma unroll
    for (int mi = 0; mi < 2; ++mi) {
        #pragma unroll
        for (int h2 = 0; h2 < 2; ++h2) {
            const int pxe = warp_m + mi * 16 + gr + 8 * h2;
            const int Pe  = tile * CTA_M + pxe;
            const int be  = Pe / HWSZ;
            const int hwe = Pe - be * HWSZ;
            float* ob = out + (size_t)be * COUT * HWSZ + hwe;
            #pragma unroll
            for (int f = 0; f < 4; ++f) {
                const int o = nh * NHALF + warp_nl + f * 8 + lq * 2;
                const float2 bi = __ldg(reinterpret_cast<const float2*>(g_bias + o));
                float v0 = d[mi][f][h2 * 2 + 0] + bi.x;
                float v1 = d[mi][f][h2 * 2 + 1] + bi.y;
                ob[(size_t)o       * HWSZ] = fmaxf(v0, 0.0f);
                ob[(size_t)(o + 1) * HWSZ] = fmaxf(v1, 0.0f);
            }
        }
    }
}

// ============================================================================
extern "C" void kernel_launch(void* const* d_in, const int* in_sizes, int n_in,
                              void* d_out, int out_size) {
    const float* x     = (const float*)d_in[0];
    const float* pw    = (const float*)d_in[1];
    const float* gamma = (const float*)d_in[2];
    const float* beta  = (const float*)d_in[3];
    const float* rmean = (const float*)d_in[4];
    const float* rvar  = (const float*)d_in[5];
    float* out = (float*)d_out;

    static bool attr_set = false;
    if (!attr_set) {
        cudaFuncSetAttribute(shiftconv_kernel,
                             cudaFuncAttributeMaxDynamicSharedMemorySize, SMEM_BYTES);
        attr_set = true;
    }

    prep_x_kernel<<<dim3(NTIL, 4), 256>>>(x, pw, gamma, beta, rmean, rvar);
    shiftconv_kernel<<<GRID, 256, SMEM_BYTES>>>(out);
}